// round 8
// baseline (speedup 1.0000x reference)
#include <cuda_runtime.h>
#include <cuda_bf16.h>
#include <cstdint>

#define NB 32
#define NS 128
#define ND 768
#define NH 12
#define HD 64
#define NM (NB*NS)   // 4096

// Job ranges (job order == dependency order; ticket issued ascending)
#define JOB_CVT   12
#define JOB_SCORE 76
#define JOB_PROD  588
#define JOB_CONS  972
#define JOB_TOT   1356
#define NCTA      296          // 2 per SM, zero wave quantization

// Scratch
__device__ __nv_bfloat16 g_nvh[NB*NS*ND];
__device__ __nv_bfloat16 g_nvl[NB*NS*ND];
__device__ __nv_bfloat16 g_Ah[NB*NS*ND];
__device__ __nv_bfloat16 g_Al[NB*NS*ND];
__device__ __nv_bfloat16 g_Wvh[ND*ND], g_Wvl[ND*ND];
__device__ __nv_bfloat16 g_Woh[ND*ND], g_Wol[ND*ND];
__device__ float g_U[NH*ND];
__device__ float g_c[NH];
__device__ float g_lg[NB*NH*NS];
// [0]=prep(12) [1]=Wv(32) [2]=Wo(32) [3+b]=score_b(16) [35+b]=prod_b(12) [67]=ticket
__device__ unsigned g_flags[68];

// ---------------------------------------------------------------------------
__device__ __forceinline__ uint32_t smem_u32(const void* p) {
    uint32_t a;
    asm("{ .reg .u64 t; cvta.to.shared.u64 t, %1; cvt.u32.u64 %0, t; }"
        : "=r"(a) : "l"(p));
    return a;
}
#define SWZ(o) ((o) ^ (((o) >> 3) & 0x70))

__device__ __forceinline__ void ldm_x4(uint32_t* r, uint32_t addr) {
    asm volatile("ldmatrix.sync.aligned.m8n8.x4.shared.b16 {%0,%1,%2,%3}, [%4];"
                 : "=r"(r[0]), "=r"(r[1]), "=r"(r[2]), "=r"(r[3]) : "r"(addr));
}
__device__ __forceinline__ void mma_bf16(float* d, const uint32_t* a, const uint32_t* b) {
    asm volatile(
        "mma.sync.aligned.m16n8k16.row.col.f32.bf16.bf16.f32 "
        "{%0,%1,%2,%3}, {%4,%5,%6,%7}, {%8,%9}, {%0,%1,%2,%3};"
        : "+f"(d[0]), "+f"(d[1]), "+f"(d[2]), "+f"(d[3])
        : "r"(a[0]), "r"(a[1]), "r"(a[2]), "r"(a[3]), "r"(b[0]), "r"(b[1]));
}
__device__ __forceinline__ void cpa16(uint32_t dst, const void* src) {
    asm volatile("cp.async.cg.shared.global [%0], [%1], 16;"
                 :: "r"(dst), "l"(src) : "memory");
}
__device__ __forceinline__ void cpa_commit() {
    asm volatile("cp.async.commit_group;" ::: "memory");
}
__device__ __forceinline__ void cpa_wait0() {
    asm volatile("cp.async.wait_group 0;" ::: "memory");
}
__device__ __forceinline__ uint32_t pack2bf(float a, float b) {
    __nv_bfloat162 t = __floats2bfloat162_rn(a, b);
    return *(uint32_t*)&t;
}
__device__ __forceinline__ float bf_hi(float x) {
    return __bfloat162float(__float2bfloat16(x));
}
__device__ __forceinline__ unsigned ld_acq(const unsigned* p) {
    unsigned v;
    asm volatile("ld.acquire.gpu.global.u32 %0, [%1];" : "=r"(v) : "l"(p));
    return v;
}
__device__ __forceinline__ void wait_flag(const unsigned* p, unsigned tgt) {
    while (ld_acq(p) < tgt) __nanosleep(64);
}
__device__ __forceinline__ void done_flag(unsigned* p) {
    __threadfence();
    atomicAdd(p, 1u);
}

// ---------------------------------------------------------------------------
// GEMM mainloop: acc = X * W^T (hi/lo bf16 split, 3-pass)
// 128(M)x64(N) tile, BK=64, 256 thr, double-buffered cp.async.
// ---------------------------------------------------------------------------
#define STG 49152
__device__ __forceinline__ void gemm_main(
    const __nv_bfloat16* __restrict__ Xh, const __nv_bfloat16* __restrict__ Xl,
    const __nv_bfloat16* __restrict__ Wh, const __nv_bfloat16* __restrict__ Wl,
    char* sm, int bm, int bn, float acc[2][4][4])
{
    const int tid = threadIdx.x;
    const int lane = tid & 31, w = tid >> 5;
    const uint32_t smb = smem_u32(sm);
    const int wm = w >> 1, wn = w & 1;

    const uint32_t a_row = (uint32_t)(wm * 32 + (lane & 15));
    const uint32_t a_kh  = (uint32_t)((lane >> 4) << 4);
    const uint32_t b_row = (uint32_t)(wn * 32 + (lane & 7) + ((lane >> 4) << 3));
    const uint32_t b_kh  = (uint32_t)(((lane >> 3) & 1) << 4);

#pragma unroll
    for (int mt = 0; mt < 2; mt++)
#pragma unroll
        for (int nt = 0; nt < 4; nt++)
#pragma unroll
            for (int i = 0; i < 4; i++) acc[mt][nt][i] = 0.f;

    auto ISSUE = [&](int c, int s) {
        const uint32_t sb = smb + s * STG;
        const int k0 = c * 64;
#pragma unroll
        for (int it = 0; it < 4; it++) {
            const int L = tid + it * 256;
            const int r = L >> 3, k8 = (L & 7);
            const uint32_t so = SWZ((uint32_t)(r * 128 + k8 * 16));
            const size_t go = (size_t)(bm + r) * ND + k0 + k8 * 8;
            cpa16(sb + so,         Xh + go);
            cpa16(sb + 16384 + so, Xl + go);
        }
#pragma unroll
        for (int it = 0; it < 2; it++) {
            const int L = tid + it * 256;
            const int r = L >> 3, k8 = (L & 7);
            const uint32_t so = SWZ((uint32_t)(r * 128 + k8 * 16));
            const size_t go = (size_t)(bn + r) * ND + k0 + k8 * 8;
            cpa16(sb + 32768 + so, Wh + go);
            cpa16(sb + 40960 + so, Wl + go);
        }
        cpa_commit();
    };

    ISSUE(0, 0);
    for (int c = 0; c < 12; c++) {
        cpa_wait0();
        __syncthreads();
        if (c < 11) ISSUE(c + 1, (c + 1) & 1);
        const uint32_t sb = smb + (c & 1) * STG;

#pragma unroll
        for (int ks = 0; ks < 4; ks++) {
            uint32_t ah[2][4], al[2][4], bh[2][4], bl[2][4];
#pragma unroll
            for (int mt = 0; mt < 2; mt++) {
                const uint32_t byo = (a_row + mt * 16) * 128 + ks * 32 + a_kh;
                ldm_x4(ah[mt], sb + SWZ(byo));
                ldm_x4(al[mt], sb + 16384 + SWZ(byo));
            }
#pragma unroll
            for (int nt2 = 0; nt2 < 2; nt2++) {
                const uint32_t byo = (b_row + nt2 * 16) * 128 + ks * 32 + b_kh;
                ldm_x4(bh[nt2], sb + 32768 + SWZ(byo));
                ldm_x4(bl[nt2], sb + 40960 + SWZ(byo));
            }
#pragma unroll
            for (int mt = 0; mt < 2; mt++)
#pragma unroll
                for (int nt = 0; nt < 4; nt++) {
                    const uint32_t* bhp = &bh[nt >> 1][(nt & 1) * 2];
                    const uint32_t* blp = &bl[nt >> 1][(nt & 1) * 2];
                    mma_bf16(acc[mt][nt], ah[mt], bhp);
                    mma_bf16(acc[mt][nt], ah[mt], blp);
                    mma_bf16(acc[mt][nt], al[mt], bhp);
                }
        }
        __syncthreads();
    }
}

// ---------------------------------------------------------------------------
// Persistent kernel: 296 CTAs pull jobs from a global ticket.
// ---------------------------------------------------------------------------
__global__ __launch_bounds__(256, 2)
void fused_all(const float* __restrict__ desc, const float* __restrict__ nv,
               const float* __restrict__ Wk, const float* __restrict__ bk,
               const float* __restrict__ Wv, const float* __restrict__ bv,
               const float* __restrict__ Wo, const float* __restrict__ bo,
               const float* __restrict__ Wa, float* __restrict__ out)
{
    extern __shared__ __align__(1024) char sm[];
    __shared__ float sp[NS];
    __shared__ float spart[8];
    __shared__ float sred[256];
    __shared__ float svs[HD];
    __shared__ float swk[HD];
    __shared__ unsigned s_job;

    const int tid = threadIdx.x;
    const int lane = tid & 31, w = tid >> 5;
    const int wm = w >> 1, wn = w & 1;

    for (;;) {
        if (tid == 0) s_job = atomicAdd(&g_flags[67], 1u);
        __syncthreads();
        const unsigned job = s_job;
        if (job >= JOB_TOT) return;
        __syncthreads();   // smem reuse guard between jobs

        if (job < JOB_CVT) {
            // ---------------- PREP: g_U[h], g_c[h] ----------------
            const int h = job;
            if (tid < HD) swk[tid] = Wa[HD + tid];
            __syncthreads();
            for (int k = tid; k < ND; k += 256) {
                float a = 0.f;
#pragma unroll 8
                for (int d = 0; d < HD; d++)
                    a += swk[d] * Wk[(size_t)(h * HD + d) * ND + k];
                g_U[h * ND + k] = a;
            }
            if (tid == 0) {
                float cc = 0.f;
                for (int d = 0; d < HD; d++) cc += swk[d] * bk[h * HD + d];
                g_c[h] = cc;
            }
            __syncthreads();
            if (tid == 0) done_flag(&g_flags[0]);

        } else if (job < JOB_SCORE) {
            // ---------------- CVT weights to hi/lo ----------------
            const int cid = job - JOB_CVT;
            const int half = cid >> 5;
            const int seg = cid & 31;
            const float* src = half ? Wo : Wv;
            uint32_t* hi = (uint32_t*)(half ? g_Woh : g_Wvh);
            uint32_t* lo = (uint32_t*)(half ? g_Wol : g_Wvl);
            const int base = seg * 4608;
#pragma unroll 2
            for (int it = 0; it < 18; it++) {
                const int lin = base + it * 256 + tid;
                float4 v = *(const float4*)(src + (size_t)lin * 4);
                float h0 = bf_hi(v.x), h1 = bf_hi(v.y), h2 = bf_hi(v.z), h3 = bf_hi(v.w);
                *(uint2*)(hi + (size_t)lin * 2) =
                    make_uint2(pack2bf(v.x, v.y), pack2bf(v.z, v.w));
                *(uint2*)(lo + (size_t)lin * 2) =
                    make_uint2(pack2bf(v.x - h0, v.y - h1), pack2bf(v.z - h2, v.w - h3));
            }
            __syncthreads();
            if (tid == 0) done_flag(&g_flags[1 + half]);

        } else if (job < JOB_PROD) {
            // ---------------- SCORE + nv split (8 rows) ----------------
            const int sid = job - JOB_SCORE;
            const int b = sid >> 4;
            const int j0 = (sid & 15) * 8;
            float* s_nv = (float*)sm;
            float* s_ds = (float*)(sm + 24576);

            if (tid == 0) wait_flag(&g_flags[0], 12u);
            __syncthreads();

            const size_t gbase = ((size_t)b * NS + j0) * ND;
            const float* src = nv + gbase;
            uint32_t* nvh = (uint32_t*)g_nvh;
            uint32_t* nvl = (uint32_t*)g_nvl;
#pragma unroll
            for (int it = 0; it < 6; it++) {
                const int lin = tid + it * 256;
                float4 v = *(const float4*)(src + lin * 4);
                *(float4*)(s_nv + lin * 4) = v;
                float h0 = bf_hi(v.x), h1 = bf_hi(v.y), h2 = bf_hi(v.z), h3 = bf_hi(v.w);
                size_t ui = gbase / 2 + (size_t)lin * 2;
                *(uint2*)(nvh + ui) = make_uint2(pack2bf(v.x, v.y), pack2bf(v.z, v.w));
                *(uint2*)(nvl + ui) =
                    make_uint2(pack2bf(v.x - h0, v.y - h1), pack2bf(v.z - h2, v.w - h3));
                const int r = lin / 192, c4 = lin % 192;
                const int drow = j0 + r - 1;
                float4 dv = (drow >= 0)
                    ? *(const float4*)(desc + ((size_t)b * (NS - 1) + drow) * ND + c4 * 4)
                    : make_float4(0.f, 0.f, 0.f, 0.f);
                *(float4*)(s_ds + r * ND + c4 * 4) = dv;
            }
            __syncthreads();

            const float we0 = Wa[2 * HD + lane], we1 = Wa[2 * HD + 32 + lane];
            for (int h = w; h < NH; h += 8) {
                float u[24];
#pragma unroll
                for (int t = 0; t < 24; t++) u[t] = g_U[h * ND + t * 32 + lane];
                const float ch = g_c[h];
#pragma unroll
                for (int j = 0; j < 8; j++) {
                    float acc = 0.f;
#pragma unroll
                    for (int t = 0; t < 24; t++)
                        acc += s_nv[j * ND + t * 32 + lane] * u[t];
                    acc += s_ds[j * ND + h * 64 + lane] * we0
                         + s_ds[j * ND + h * 64 + 32 + lane] * we1;
#pragma unroll
                    for (int off = 16; off > 0; off >>= 1)
                        acc += __shfl_xor_sync(0xFFFFFFFF, acc, off);
                    if (lane == 0)
                        g_lg[((size_t)b * NH + h) * NS + j0 + j] =
                            (j0 + j >= 1) ? acc + ch : 0.f;
                }
            }
            __syncthreads();
            if (tid == 0) done_flag(&g_flags[3 + b]);

        } else if (job < JOB_CONS) {
            // ------------- PRODUCER: V proj + softmax + attention ----------
            const int pid = job - JOB_PROD;
            const int h = pid % NH, b = pid / NH;
            const int bm = b * 128, bn = h * 64;

            if (tid == 0) {
                wait_flag(&g_flags[3 + b], 16u);
                wait_flag(&g_flags[1], 32u);
            }
            __syncthreads();

            const float* lg = g_lg + ((size_t)b * NH + h) * NS;
            float l = -1e30f;
            if (tid >= 1 && tid < NS) l = lg[tid];
            float wmx = l;
#pragma unroll
            for (int off = 16; off > 0; off >>= 1)
                wmx = fmaxf(wmx, __shfl_xor_sync(0xFFFFFFFF, wmx, off));
            if (lane == 0 && w < 4) spart[w] = wmx;
            __syncthreads();
            const float m = fmaxf(fmaxf(spart[0], spart[1]),
                                  fmaxf(spart[2], spart[3]));
            const float pe = (tid >= 1 && tid < NS) ? expf(l - m) : 0.f;
            if (tid < NS) sp[tid] = pe;
            float ws = pe;
#pragma unroll
            for (int off = 16; off > 0; off >>= 1)
                ws += __shfl_xor_sync(0xFFFFFFFF, ws, off);
            if (lane == 0 && w < 4) spart[4 + w] = ws;
            __syncthreads();

            float acc[2][4][4];
            gemm_main(g_nvh, g_nvl, g_Wvh, g_Wvl, sm, bm, bn, acc);

            float* sVt = (float*)sm;
            const int r_base = wm * 32 + (lane >> 2);
            const int c_base = wn * 32 + ((lane & 3) << 1);
#pragma unroll
            for (int mt = 0; mt < 2; mt++)
#pragma unroll
                for (int nt = 0; nt < 4; nt++) {
                    const int c = c_base + nt * 8;
                    const float b0 = bv[bn + c], b1 = bv[bn + c + 1];
                    const int r0 = r_base + mt * 16;
                    *(float2*)&sVt[r0 * 64 + c] =
                        make_float2(acc[mt][nt][0] + b0, acc[mt][nt][1] + b1);
                    *(float2*)&sVt[(r0 + 8) * 64 + c] =
                        make_float2(acc[mt][nt][2] + b0, acc[mt][nt][3] + b1);
                }
            __syncthreads();

            const float S = spart[4] + spart[5] + spart[6] + spart[7];
            const int d = tid & 63;
            const int q = tid >> 6;
            float av = 0.f;
#pragma unroll 4
            for (int j = q; j < NS; j += 4) av += sp[j] * sVt[j * 64 + d];
            sred[tid] = av;
            __syncthreads();
            if (tid < HD)
                svs[tid] = sred[tid] + sred[tid + 64] + sred[tid + 128] + sred[tid + 192];
            __syncthreads();

            const float vs = svs[d];
            __nv_bfloat16* pAh = g_Ah + ((size_t)b * NS) * ND + bn + d;
            __nv_bfloat16* pAl = g_Al + ((size_t)b * NS) * ND + bn + d;
#pragma unroll 4
            for (int i = q; i < NS; i += 4) {
                const float pi = sp[i];
                const float val = __fdividef(vs - pi * sVt[i * 64 + d], S - pi);
                const float hi = bf_hi(val);
                pAh[(size_t)i * ND] = __float2bfloat16(val);
                pAl[(size_t)i * ND] = __float2bfloat16(val - hi);
            }
            __syncthreads();
            if (tid == 0) done_flag(&g_flags[35 + b]);

        } else {
            // ---------------- CONSUMER: out projection ----------------
            const int cid = job - JOB_CONS;
            const int bn = (cid % 12) * 64;
            const int b  = cid / 12;
            const int bm = b * 128;

            if (tid == 0) {
                wait_flag(&g_flags[35 + b], 12u);
                wait_flag(&g_flags[2], 32u);
            }
            __syncthreads();

            float acc[2][4][4];
            gemm_main(g_Ah, g_Al, g_Woh, g_Wol, sm, bm, bn, acc);

            const int erow = bm + wm * 32 + (lane >> 2);
            const int ecol0 = bn + wn * 32 + ((lane & 3) << 1);
#pragma unroll
            for (int mt = 0; mt < 2; mt++)
#pragma unroll
                for (int nt = 0; nt < 4; nt++) {
                    const int col = ecol0 + nt * 8;
                    const float b0 = bo[col], b1 = bo[col + 1];
                    const int r0 = erow + mt * 16;
                    *(float2*)(out + (size_t)r0 * ND + col) =
                        make_float2(acc[mt][nt][0] + b0, acc[mt][nt][1] + b1);
                    *(float2*)(out + (size_t)(r0 + 8) * ND + col) =
                        make_float2(acc[mt][nt][2] + b0, acc[mt][nt][3] + b1);
                }
            __syncthreads();
        }
    }
}

// ---------------------------------------------------------------------------
extern "C" void kernel_launch(void* const* d_in, const int* in_sizes, int n_in,
                              void* d_out, int out_size)
{
    const float* desc = (const float*)d_in[0];
    const float* nv   = (const float*)d_in[1];
    // d_in[2]=Wq, d_in[3]=bq dead; d_in[11]=ba dead (cancel in softmax)
    const float* Wk   = (const float*)d_in[4];
    const float* bk   = (const float*)d_in[5];
    const float* Wv   = (const float*)d_in[6];
    const float* bv   = (const float*)d_in[7];
    const float* Wo   = (const float*)d_in[8];
    const float* bo   = (const float*)d_in[9];
    const float* Wa   = (const float*)d_in[10];
    float* out = (float*)d_out;

    cudaFuncSetAttribute(fused_all, cudaFuncAttributeMaxDynamicSharedMemorySize, 2 * STG);

    unsigned* pflag;
    cudaGetSymbolAddress((void**)&pflag, g_flags);
    cudaMemsetAsync(pflag, 0, 68 * sizeof(unsigned), 0);

    fused_all<<<NCTA, 256, 2 * STG>>>(desc, nv, Wk, bk, Wv, bv, Wo, bo, Wa, out);
}

// round 9
// speedup vs baseline: 1.2782x; 1.2782x over previous
#include <cuda_runtime.h>
#include <cuda_bf16.h>
#include <cuda_fp16.h>
#include <cstdint>

#define NB 32
#define NS 128
#define ND 768
#define NH 12
#define HD 64
#define NM (NB*NS)   // 4096

// CTA role ranges (bid order == dependency order; HW dispatches ascending)
#define BID_CVT   12
#define BID_SCORE 76
#define BID_PROD  588
#define BID_CONS  972
#define GRID_TOT  1356

// Scratch (fp16 activations hi/lo, fp16 weights single)
__device__ __half g_nvh[NB*NS*ND];
__device__ __half g_nvl[NB*NS*ND];
__device__ __half g_Ah[NB*NS*ND];
__device__ __half g_Al[NB*NS*ND];
__device__ __half g_Wvf[ND*ND];
__device__ __half g_Wof[ND*ND];
__device__ float g_U[NH*ND];
__device__ float g_c[NH];
__device__ float g_lg[NB*NH*NS];
// flags: [0]=prep(12) [1]=Wv(32) [2]=Wo(32) [3+b]=score_b(16) [35+b]=prod_b(12)
__device__ unsigned g_flags[3 + NB + NB];

// ---------------------------------------------------------------------------
__device__ __forceinline__ uint32_t smem_u32(const void* p) {
    uint32_t a;
    asm("{ .reg .u64 t; cvta.to.shared.u64 t, %1; cvt.u32.u64 %0, t; }"
        : "=r"(a) : "l"(p));
    return a;
}
#define SWZ(o) ((o) ^ (((o) >> 3) & 0x70))

__device__ __forceinline__ void ldm_x4(uint32_t* r, uint32_t addr) {
    asm volatile("ldmatrix.sync.aligned.m8n8.x4.shared.b16 {%0,%1,%2,%3}, [%4];"
                 : "=r"(r[0]), "=r"(r[1]), "=r"(r[2]), "=r"(r[3]) : "r"(addr));
}
__device__ __forceinline__ void mma_f16(float* d, const uint32_t* a, const uint32_t* b) {
    asm volatile(
        "mma.sync.aligned.m16n8k16.row.col.f32.f16.f16.f32 "
        "{%0,%1,%2,%3}, {%4,%5,%6,%7}, {%8,%9}, {%0,%1,%2,%3};"
        : "+f"(d[0]), "+f"(d[1]), "+f"(d[2]), "+f"(d[3])
        : "r"(a[0]), "r"(a[1]), "r"(a[2]), "r"(a[3]), "r"(b[0]), "r"(b[1]));
}
__device__ __forceinline__ void cpa16(uint32_t dst, const void* src) {
    asm volatile("cp.async.cg.shared.global [%0], [%1], 16;"
                 :: "r"(dst), "l"(src) : "memory");
}
__device__ __forceinline__ void cpa_commit() {
    asm volatile("cp.async.commit_group;" ::: "memory");
}
__device__ __forceinline__ void cpa_wait0() {
    asm volatile("cp.async.wait_group 0;" ::: "memory");
}
__device__ __forceinline__ uint32_t pack2h(float a, float b) {
    __half2 t = __floats2half2_rn(a, b);
    return *(uint32_t*)&t;
}
__device__ __forceinline__ float h_hi(float x) {
    return __half2float(__float2half(x));
}
__device__ __forceinline__ unsigned ld_acq(const unsigned* p) {
    unsigned v;
    asm volatile("ld.acquire.gpu.global.u32 %0, [%1];" : "=r"(v) : "l"(p));
    return v;
}
__device__ __forceinline__ void wait_flag(const unsigned* p, unsigned tgt) {
    while (ld_acq(p) < tgt) __nanosleep(64);
}
__device__ __forceinline__ void done_flag(unsigned* p) {
    __threadfence();
    atomicAdd(p, 1u);
}

// ---------------------------------------------------------------------------
// GEMM mainloop: acc = (Xh + Xl) * Wf^T   (fp16 2-pass split on activations)
// 128(M)x64(N) tile, BK=64, 256 thr, double-buffered cp.async.
// Smem stage 40KB: A_hi@0 (16K), A_lo@16K (16K), B@32K (8K). SW128 swizzle.
// ---------------------------------------------------------------------------
#define STG 40960
__device__ __forceinline__ void gemm_main(
    const __half* __restrict__ Xh, const __half* __restrict__ Xl,
    const __half* __restrict__ Wf,
    char* sm, int bm, int bn, float acc[2][4][4])
{
    const int tid = threadIdx.x;
    const int lane = tid & 31, w = tid >> 5;
    const uint32_t smb = smem_u32(sm);
    const int wm = w >> 1, wn = w & 1;

    const uint32_t a_row = (uint32_t)(wm * 32 + (lane & 15));
    const uint32_t a_kh  = (uint32_t)((lane >> 4) << 4);
    const uint32_t b_row = (uint32_t)(wn * 32 + (lane & 7) + ((lane >> 4) << 3));
    const uint32_t b_kh  = (uint32_t)(((lane >> 3) & 1) << 4);

#pragma unroll
    for (int mt = 0; mt < 2; mt++)
#pragma unroll
        for (int nt = 0; nt < 4; nt++)
#pragma unroll
            for (int i = 0; i < 4; i++) acc[mt][nt][i] = 0.f;

    auto ISSUE = [&](int c, int s) {
        const uint32_t sb = smb + s * STG;
        const int k0 = c * 64;
#pragma unroll
        for (int it = 0; it < 4; it++) {             // A: 128 rows x 8 k8-blocks
            const int L = tid + it * 256;
            const int r = L >> 3, k8 = (L & 7);
            const uint32_t so = SWZ((uint32_t)(r * 128 + k8 * 16));
            const size_t go = (size_t)(bm + r) * ND + k0 + k8 * 8;
            cpa16(sb + so,         Xh + go);
            cpa16(sb + 16384 + so, Xl + go);
        }
        {                                             // B: 64 rows x 8 k8-blocks
            const int L = tid;                        // 512 chunks, 256 thr x 2
#pragma unroll
            for (int it = 0; it < 2; it++) {
                const int LL = L + it * 256;
                const int r = LL >> 3, k8 = (LL & 7);
                const uint32_t so = SWZ((uint32_t)(r * 128 + k8 * 16));
                const size_t go = (size_t)(bn + r) * ND + k0 + k8 * 8;
                cpa16(sb + 32768 + so, Wf + go);
            }
        }
        cpa_commit();
    };

    ISSUE(0, 0);
    for (int c = 0; c < 12; c++) {
        cpa_wait0();
        __syncthreads();
        if (c < 11) ISSUE(c + 1, (c + 1) & 1);
        const uint32_t sb = smb + (c & 1) * STG;

#pragma unroll
        for (int ks = 0; ks < 4; ks++) {
            uint32_t ah[2][4], al[2][4], bf[2][4];
#pragma unroll
            for (int mt = 0; mt < 2; mt++) {
                const uint32_t byo = (a_row + mt * 16) * 128 + ks * 32 + a_kh;
                ldm_x4(ah[mt], sb + SWZ(byo));
                ldm_x4(al[mt], sb + 16384 + SWZ(byo));
            }
#pragma unroll
            for (int nt2 = 0; nt2 < 2; nt2++) {
                const uint32_t byo = (b_row + nt2 * 16) * 128 + ks * 32 + b_kh;
                ldm_x4(bf[nt2], sb + 32768 + SWZ(byo));
            }
#pragma unroll
            for (int mt = 0; mt < 2; mt++)
#pragma unroll
                for (int nt = 0; nt < 4; nt++) {
                    const uint32_t* bp = &bf[nt >> 1][(nt & 1) * 2];
                    mma_f16(acc[mt][nt], ah[mt], bp);
                    mma_f16(acc[mt][nt], al[mt], bp);
                }
        }
        __syncthreads();
    }
}

// ---------------------------------------------------------------------------
// ONE kernel, flag-gated phases (static bid mapping, R7 scheme).
// ---------------------------------------------------------------------------
__global__ __launch_bounds__(256, 2)
void fused_all(const float* __restrict__ desc, const float* __restrict__ nv,
               const float* __restrict__ Wk, const float* __restrict__ bk,
               const float* __restrict__ Wv, const float* __restrict__ bv,
               const float* __restrict__ Wo, const float* __restrict__ bo,
               const float* __restrict__ Wa, float* __restrict__ out)
{
    extern __shared__ __align__(1024) char sm[];
    __shared__ float sp[NS];
    __shared__ float spart[8];
    __shared__ float sred[256];
    __shared__ float svs[HD];
    __shared__ float swk[HD];

    const int bid = blockIdx.x;
    const int tid = threadIdx.x;
    const int lane = tid & 31, w = tid >> 5;
    const int wm = w >> 1, wn = w & 1;

    if (bid < BID_CVT) {
        // ---------------- PREP: g_U[h], g_c[h] ----------------
        const int h = bid;
        if (tid < HD) swk[tid] = Wa[HD + tid];
        __syncthreads();
        for (int k = tid; k < ND; k += 256) {
            float a = 0.f;
#pragma unroll 8
            for (int d = 0; d < HD; d++)
                a += swk[d] * Wk[(size_t)(h * HD + d) * ND + k];
            g_U[h * ND + k] = a;
        }
        if (tid == 0) {
            float cc = 0.f;
            for (int d = 0; d < HD; d++) cc += swk[d] * bk[h * HD + d];
            g_c[h] = cc;
        }
        __syncthreads();
        if (tid == 0) done_flag(&g_flags[0]);

    } else if (bid < BID_SCORE) {
        // ---------------- CVT weights to fp16 ----------------
        const int cid = bid - BID_CVT;
        const int half_sel = cid >> 5;        // 0=Wv 1=Wo
        const int seg = cid & 31;
        const float* src = half_sel ? Wo : Wv;
        uint32_t* dst = (uint32_t*)(half_sel ? g_Wof : g_Wvf);
        const int base = seg * 4608;          // f4 units; 147456/32
#pragma unroll 2
        for (int it = 0; it < 18; it++) {
            const int lin = base + it * 256 + tid;
            float4 v = *(const float4*)(src + (size_t)lin * 4);
            *(uint2*)(dst + (size_t)lin * 2) =
                make_uint2(pack2h(v.x, v.y), pack2h(v.z, v.w));
        }
        __syncthreads();
        if (tid == 0) done_flag(&g_flags[1 + half_sel]);

    } else if (bid < BID_PROD) {
        // ---------------- SCORE + nv hi/lo split (8 rows) ----------------
        const int sid = bid - BID_SCORE;
        const int b = sid >> 4;
        const int j0 = (sid & 15) * 8;
        float* s_nv = (float*)sm;                    // 8x768
        float* s_ds = (float*)(sm + 24576);          // 8x768

        if (tid == 0) wait_flag(&g_flags[0], 12u);
        __syncthreads();

        const size_t gbase = ((size_t)b * NS + j0) * ND;
        const float* src = nv + gbase;
        uint32_t* nvh = (uint32_t*)g_nvh;
        uint32_t* nvl = (uint32_t*)g_nvl;
#pragma unroll
        for (int it = 0; it < 6; it++) {
            const int lin = tid + it * 256;          // 0..1535 f4
            float4 v = *(const float4*)(src + lin * 4);
            *(float4*)(s_nv + lin * 4) = v;
            float h0 = h_hi(v.x), h1 = h_hi(v.y), h2 = h_hi(v.z), h3 = h_hi(v.w);
            size_t ui = gbase / 2 + (size_t)lin * 2;
            *(uint2*)(nvh + ui) = make_uint2(pack2h(v.x, v.y), pack2h(v.z, v.w));
            *(uint2*)(nvl + ui) =
                make_uint2(pack2h(v.x - h0, v.y - h1), pack2h(v.z - h2, v.w - h3));
            const int r = lin / 192, c4 = lin % 192;
            const int drow = j0 + r - 1;
            float4 dv = (drow >= 0)
                ? *(const float4*)(desc + ((size_t)b * (NS - 1) + drow) * ND + c4 * 4)
                : make_float4(0.f, 0.f, 0.f, 0.f);
            *(float4*)(s_ds + r * ND + c4 * 4) = dv;
        }
        __syncthreads();

        const float we0 = Wa[2 * HD + lane], we1 = Wa[2 * HD + 32 + lane];
        for (int h = w; h < NH; h += 8) {
            float u[24];
#pragma unroll
            for (int t = 0; t < 24; t++) u[t] = g_U[h * ND + t * 32 + lane];
            const float ch = g_c[h];
#pragma unroll
            for (int j = 0; j < 8; j++) {
                float acc = 0.f;
#pragma unroll
                for (int t = 0; t < 24; t++)
                    acc += s_nv[j * ND + t * 32 + lane] * u[t];
                acc += s_ds[j * ND + h * 64 + lane] * we0
                     + s_ds[j * ND + h * 64 + 32 + lane] * we1;
#pragma unroll
                for (int off = 16; off > 0; off >>= 1)
                    acc += __shfl_xor_sync(0xFFFFFFFF, acc, off);
                if (lane == 0)
                    g_lg[((size_t)b * NH + h) * NS + j0 + j] =
                        (j0 + j >= 1) ? acc + ch : 0.f;
            }
        }
        __syncthreads();
        if (tid == 0) done_flag(&g_flags[3 + b]);

    } else if (bid < BID_CONS) {
        // ------------- PRODUCER: V proj + softmax + attention ----------
        const int pid = bid - BID_PROD;
        const int h = pid % NH, b = pid / NH;
        const int bm = b * 128, bn = h * 64;

        if (tid == 0) {
            wait_flag(&g_flags[3 + b], 16u);
            wait_flag(&g_flags[1], 32u);
        }
        __syncthreads();

        const float* lg = g_lg + ((size_t)b * NH + h) * NS;
        float l = -1e30f;
        if (tid >= 1 && tid < NS) l = lg[tid];
        float wmx = l;
#pragma unroll
        for (int off = 16; off > 0; off >>= 1)
            wmx = fmaxf(wmx, __shfl_xor_sync(0xFFFFFFFF, wmx, off));
        if (lane == 0 && w < 4) spart[w] = wmx;
        __syncthreads();
        const float m = fmaxf(fmaxf(spart[0], spart[1]), fmaxf(spart[2], spart[3]));
        const float pe = (tid >= 1 && tid < NS) ? expf(l - m) : 0.f;
        if (tid < NS) sp[tid] = pe;
        float ws = pe;
#pragma unroll
        for (int off = 16; off > 0; off >>= 1)
            ws += __shfl_xor_sync(0xFFFFFFFF, ws, off);
        if (lane == 0 && w < 4) spart[4 + w] = ws;
        __syncthreads();

        float acc[2][4][4];
        gemm_main(g_nvh, g_nvl, g_Wvf, sm, bm, bn, acc);

        float* sVt = (float*)sm;
        const int r_base = wm * 32 + (lane >> 2);
        const int c_base = wn * 32 + ((lane & 3) << 1);
#pragma unroll
        for (int mt = 0; mt < 2; mt++)
#pragma unroll
            for (int nt = 0; nt < 4; nt++) {
                const int c = c_base + nt * 8;
                const float b0 = bv[bn + c], b1 = bv[bn + c + 1];
                const int r0 = r_base + mt * 16;
                *(float2*)&sVt[r0 * 64 + c] =
                    make_float2(acc[mt][nt][0] + b0, acc[mt][nt][1] + b1);
                *(float2*)&sVt[(r0 + 8) * 64 + c] =
                    make_float2(acc[mt][nt][2] + b0, acc[mt][nt][3] + b1);
            }
        __syncthreads();

        const float S = spart[4] + spart[5] + spart[6] + spart[7];
        const int d = tid & 63;
        const int q = tid >> 6;
        float av = 0.f;
#pragma unroll 4
        for (int j = q; j < NS; j += 4) av += sp[j] * sVt[j * 64 + d];
        sred[tid] = av;
        __syncthreads();
        if (tid < HD)
            svs[tid] = sred[tid] + sred[tid + 64] + sred[tid + 128] + sred[tid + 192];
        __syncthreads();

        const float vs = svs[d];
        __half* pAh = g_Ah + ((size_t)b * NS) * ND + bn + d;
        __half* pAl = g_Al + ((size_t)b * NS) * ND + bn + d;
#pragma unroll 4
        for (int i = q; i < NS; i += 4) {
            const float pi = sp[i];
            const float val = __fdividef(vs - pi * sVt[i * 64 + d], S - pi);
            const float hi = h_hi(val);
            pAh[(size_t)i * ND] = __float2half(val);
            pAl[(size_t)i * ND] = __float2half(val - hi);
        }
        __syncthreads();
        if (tid == 0) done_flag(&g_flags[35 + b]);

    } else {
        // ---------------- CONSUMER: out projection ----------------
        const int cid = bid - BID_CONS;
        const int bn = (cid % 12) * 64;
        const int b  = cid / 12;
        const int bm = b * 128;

        if (tid == 0) {
            wait_flag(&g_flags[35 + b], 12u);
            wait_flag(&g_flags[2], 32u);
        }
        __syncthreads();

        float acc[2][4][4];
        gemm_main(g_Ah, g_Al, g_Wof, sm, bm, bn, acc);

        const int erow = bm + wm * 32 + (lane >> 2);
        const int ecol0 = bn + wn * 32 + ((lane & 3) << 1);
#pragma unroll
        for (int mt = 0; mt < 2; mt++)
#pragma unroll
            for (int nt = 0; nt < 4; nt++) {
                const int col = ecol0 + nt * 8;
                const float b0 = bo[col], b1 = bo[col + 1];
                const int r0 = erow + mt * 16;
                *(float2*)(out + (size_t)r0 * ND + col) =
                    make_float2(acc[mt][nt][0] + b0, acc[mt][nt][1] + b1);
                *(float2*)(out + (size_t)(r0 + 8) * ND + col) =
                    make_float2(acc[mt][nt][2] + b0, acc[mt][nt][3] + b1);
            }
    }
}

// ---------------------------------------------------------------------------
extern "C" void kernel_launch(void* const* d_in, const int* in_sizes, int n_in,
                              void* d_out, int out_size)
{
    const float* desc = (const float*)d_in[0];
    const float* nv   = (const float*)d_in[1];
    // d_in[2]=Wq, d_in[3]=bq dead; d_in[11]=ba dead (cancel in softmax)
    const float* Wk   = (const float*)d_in[4];
    const float* bk   = (const float*)d_in[5];
    const float* Wv   = (const float*)d_in[6];
    const float* bv   = (const float*)d_in[7];
    const float* Wo   = (const float*)d_in[8];
    const float* bo   = (const float*)d_in[9];
    const float* Wa   = (const float*)d_in[10];
    float* out = (float*)d_out;

    cudaFuncSetAttribute(fused_all, cudaFuncAttributeMaxDynamicSharedMemorySize, 2 * STG);

    unsigned* pflag;
    cudaGetSymbolAddress((void**)&pflag, g_flags);
    cudaMemsetAsync(pflag, 0, (3 + NB + NB) * sizeof(unsigned), 0);

    fused_all<<<GRID_TOT, 256, 2 * STG>>>(desc, nv, Wk, bk, Wv, bv, Wo, bo, Wa, out);
}

// round 10
// speedup vs baseline: 2.0210x; 1.5811x over previous
#include <cuda_runtime.h>
#include <cuda_fp16.h>
#include <cstdint>

#define NB 32
#define NS 128
#define ND 768
#define NH 12
#define HD 64
#define NM (NB*NS)   // 4096

// CTA role ranges (bid order == dependency order; HW dispatches ascending)
#define BID_CVT   12
#define BID_SCORE 76
#define BID_PROD  588
#define BID_CONS  972
#define GRID_TOT  1356

// Scratch (single fp16 everywhere)
__device__ __half g_nvf[NB*NS*ND];
__device__ __half g_Af[NB*NS*ND];
__device__ __half g_Wvf[ND*ND];
__device__ __half g_Wof[ND*ND];
__device__ float g_U[NH*ND];
__device__ float g_c[NH];
__device__ float g_lg[NB*NH*NS];
// flags: [0]=prep(12) [1]=Wv(32) [2]=Wo(32) [3+b]=score_b(16) [35+b]=prod_b(12)
__device__ unsigned g_flags[3 + NB + NB];

// ---------------------------------------------------------------------------
__device__ __forceinline__ uint32_t smem_u32(const void* p) {
    uint32_t a;
    asm("{ .reg .u64 t; cvta.to.shared.u64 t, %1; cvt.u32.u64 %0, t; }"
        : "=r"(a) : "l"(p));
    return a;
}
#define SWZ(o) ((o) ^ (((o) >> 3) & 0x70))

__device__ __forceinline__ void ldm_x4(uint32_t* r, uint32_t addr) {
    asm volatile("ldmatrix.sync.aligned.m8n8.x4.shared.b16 {%0,%1,%2,%3}, [%4];"
                 : "=r"(r[0]), "=r"(r[1]), "=r"(r[2]), "=r"(r[3]) : "r"(addr));
}
__device__ __forceinline__ void mma_f16(float* d, const uint32_t* a, const uint32_t* b) {
    asm volatile(
        "mma.sync.aligned.m16n8k16.row.col.f32.f16.f16.f32 "
        "{%0,%1,%2,%3}, {%4,%5,%6,%7}, {%8,%9}, {%0,%1,%2,%3};"
        : "+f"(d[0]), "+f"(d[1]), "+f"(d[2]), "+f"(d[3])
        : "r"(a[0]), "r"(a[1]), "r"(a[2]), "r"(a[3]), "r"(b[0]), "r"(b[1]));
}
__device__ __forceinline__ void cpa16(uint32_t dst, const void* src) {
    asm volatile("cp.async.cg.shared.global [%0], [%1], 16;"
                 :: "r"(dst), "l"(src) : "memory");
}
__device__ __forceinline__ void cpa_commit() {
    asm volatile("cp.async.commit_group;" ::: "memory");
}
__device__ __forceinline__ void cpa_wait0() {
    asm volatile("cp.async.wait_group 0;" ::: "memory");
}
__device__ __forceinline__ void cpa_wait1() {
    asm volatile("cp.async.wait_group 1;" ::: "memory");
}
__device__ __forceinline__ uint32_t pack2h(float a, float b) {
    __half2 t = __floats2half2_rn(a, b);
    return *(uint32_t*)&t;
}
__device__ __forceinline__ unsigned ld_acq(const unsigned* p) {
    unsigned v;
    asm volatile("ld.acquire.gpu.global.u32 %0, [%1];" : "=r"(v) : "l"(p));
    return v;
}
__device__ __forceinline__ void wait_flag(const unsigned* p, unsigned tgt) {
    while (ld_acq(p) < tgt) __nanosleep(64);
}
__device__ __forceinline__ void done_flag(unsigned* p) {
    __threadfence();
    atomicAdd(p, 1u);
}

// ---------------------------------------------------------------------------
// GEMM mainloop: acc = Xf * Wf^T  (single fp16, fp32 accum)
// 128(M)x64(N) tile, BK=64, 256 thr, 3-stage cp.async pipeline.
// Stage 24KB: A@0 (16K), B@16K (8K). SW128 swizzle.
// ---------------------------------------------------------------------------
#define STG 24576
__device__ __forceinline__ void gemm_main(
    const __half* __restrict__ Xf, const __half* __restrict__ Wf,
    char* sm, int bm, int bn, float acc[2][4][4])
{
    const int tid = threadIdx.x;
    const int lane = tid & 31, w = tid >> 5;
    const uint32_t smb = smem_u32(sm);
    const int wm = w >> 1, wn = w & 1;

    const uint32_t a_row = (uint32_t)(wm * 32 + (lane & 15));
    const uint32_t a_kh  = (uint32_t)((lane >> 4) << 4);
    const uint32_t b_row = (uint32_t)(wn * 32 + (lane & 7) + ((lane >> 4) << 3));
    const uint32_t b_kh  = (uint32_t)(((lane >> 3) & 1) << 4);

#pragma unroll
    for (int mt = 0; mt < 2; mt++)
#pragma unroll
        for (int nt = 0; nt < 4; nt++)
#pragma unroll
            for (int i = 0; i < 4; i++) acc[mt][nt][i] = 0.f;

    auto ISSUE = [&](int c, int s) {
        const uint32_t sb = smb + s * STG;
        const int k0 = c * 64;
#pragma unroll
        for (int it = 0; it < 4; it++) {             // A: 128 rows x 8 k8-blocks
            const int L = tid + it * 256;
            const int r = L >> 3, k8 = (L & 7);
            const uint32_t so = SWZ((uint32_t)(r * 128 + k8 * 16));
            cpa16(sb + so, Xf + (size_t)(bm + r) * ND + k0 + k8 * 8);
        }
#pragma unroll
        for (int it = 0; it < 2; it++) {             // B: 64 rows x 8 k8-blocks
            const int L = tid + it * 256;
            const int r = L >> 3, k8 = (L & 7);
            const uint32_t so = SWZ((uint32_t)(r * 128 + k8 * 16));
            cpa16(sb + 16384 + so, Wf + (size_t)(bn + r) * ND + k0 + k8 * 8);
        }
        cpa_commit();
    };

    ISSUE(0, 0);
    ISSUE(1, 1);
    for (int c = 0; c < 12; c++) {
        if (c == 11) cpa_wait0(); else cpa_wait1();
        __syncthreads();
        if (c < 10) ISSUE(c + 2, (c + 2) % 3);
        const uint32_t sb = smb + (c % 3) * STG;

#pragma unroll
        for (int ks = 0; ks < 4; ks++) {
            uint32_t af[2][4], bf[2][4];
#pragma unroll
            for (int mt = 0; mt < 2; mt++) {
                const uint32_t byo = (a_row + mt * 16) * 128 + ks * 32 + a_kh;
                ldm_x4(af[mt], sb + SWZ(byo));
            }
#pragma unroll
            for (int nt2 = 0; nt2 < 2; nt2++) {
                const uint32_t byo = (b_row + nt2 * 16) * 128 + ks * 32 + b_kh;
                ldm_x4(bf[nt2], sb + 16384 + SWZ(byo));
            }
#pragma unroll
            for (int mt = 0; mt < 2; mt++)
#pragma unroll
                for (int nt = 0; nt < 4; nt++) {
                    const uint32_t* bp = &bf[nt >> 1][(nt & 1) * 2];
                    mma_f16(acc[mt][nt], af[mt], bp);
                }
        }
        __syncthreads();
    }
}

// ---------------------------------------------------------------------------
// ONE kernel, flag-gated phases (static bid mapping).
// ---------------------------------------------------------------------------
__global__ __launch_bounds__(256, 2)
void fused_all(const float* __restrict__ desc, const float* __restrict__ nv,
               const float* __restrict__ Wk, const float* __restrict__ bk,
               const float* __restrict__ Wv, const float* __restrict__ bv,
               const float* __restrict__ Wo, const float* __restrict__ bo,
               const float* __restrict__ Wa, float* __restrict__ out)
{
    extern __shared__ __align__(1024) char sm[];
    __shared__ float sp[NS];
    __shared__ float spart[8];
    __shared__ float sred[256];
    __shared__ float svs[HD];
    __shared__ float swk[HD];

    const int bid = blockIdx.x;
    const int tid = threadIdx.x;
    const int lane = tid & 31, w = tid >> 5;
    const int wm = w >> 1, wn = w & 1;

    if (bid < BID_CVT) {
        // ---------------- PREP: g_U[h], g_c[h] ----------------
        const int h = bid;
        if (tid < HD) swk[tid] = Wa[HD + tid];
        __syncthreads();
        for (int k = tid; k < ND; k += 256) {
            float a = 0.f;
#pragma unroll 8
            for (int d = 0; d < HD; d++)
                a += swk[d] * Wk[(size_t)(h * HD + d) * ND + k];
            g_U[h * ND + k] = a;
        }
        if (tid == 0) {
            float cc = 0.f;
            for (int d = 0; d < HD; d++) cc += swk[d] * bk[h * HD + d];
            g_c[h] = cc;
        }
        __syncthreads();
        if (tid == 0) done_flag(&g_flags[0]);

    } else if (bid < BID_SCORE) {
        // ---------------- CVT weights to fp16 ----------------
        const int cid = bid - BID_CVT;
        const int half_sel = cid >> 5;        // 0=Wv 1=Wo
        const int seg = cid & 31;
        const float* src = half_sel ? Wo : Wv;
        uint32_t* dst = (uint32_t*)(half_sel ? g_Wof : g_Wvf);
        const int base = seg * 4608;          // f4 units; 147456/32
#pragma unroll 2
        for (int it = 0; it < 18; it++) {
            const int lin = base + it * 256 + tid;
            float4 v = *(const float4*)(src + (size_t)lin * 4);
            *(uint2*)(dst + (size_t)lin * 2) =
                make_uint2(pack2h(v.x, v.y), pack2h(v.z, v.w));
        }
        __syncthreads();
        if (tid == 0) done_flag(&g_flags[1 + half_sel]);

    } else if (bid < BID_PROD) {
        // ---------------- SCORE + nv fp16 cvt (8 rows) ----------------
        const int sid = bid - BID_SCORE;
        const int b = sid >> 4;
        const int j0 = (sid & 15) * 8;
        float* s_nv = (float*)sm;                    // 8x768
        float* s_ds = (float*)(sm + 24576);          // 8x768

        if (tid == 0) wait_flag(&g_flags[0], 12u);
        __syncthreads();

        const size_t gbase = ((size_t)b * NS + j0) * ND;
        const float* src = nv + gbase;
        uint32_t* nvf = (uint32_t*)g_nvf;
#pragma unroll
        for (int it = 0; it < 6; it++) {
            const int lin = tid + it * 256;          // 0..1535 f4
            float4 v = *(const float4*)(src + lin * 4);
            *(float4*)(s_nv + lin * 4) = v;
            *(uint2*)(nvf + gbase / 2 + (size_t)lin * 2) =
                make_uint2(pack2h(v.x, v.y), pack2h(v.z, v.w));
            const int r = lin / 192, c4 = lin % 192;
            const int drow = j0 + r - 1;
            float4 dv = (drow >= 0)
                ? *(const float4*)(desc + ((size_t)b * (NS - 1) + drow) * ND + c4 * 4)
                : make_float4(0.f, 0.f, 0.f, 0.f);
            *(float4*)(s_ds + r * ND + c4 * 4) = dv;
        }
        __syncthreads();

        const float we0 = Wa[2 * HD + lane], we1 = Wa[2 * HD + 32 + lane];
        for (int h = w; h < NH; h += 8) {
            float u[24];
#pragma unroll
            for (int t = 0; t < 24; t++) u[t] = g_U[h * ND + t * 32 + lane];
            const float ch = g_c[h];
#pragma unroll
            for (int j = 0; j < 8; j++) {
                float acc = 0.f;
#pragma unroll
                for (int t = 0; t < 24; t++)
                    acc += s_nv[j * ND + t * 32 + lane] * u[t];
                acc += s_ds[j * ND + h * 64 + lane] * we0
                     + s_ds[j * ND + h * 64 + 32 + lane] * we1;
#pragma unroll
                for (int off = 16; off > 0; off >>= 1)
                    acc += __shfl_xor_sync(0xFFFFFFFF, acc, off);
                if (lane == 0)
                    g_lg[((size_t)b * NH + h) * NS + j0 + j] =
                        (j0 + j >= 1) ? acc + ch : 0.f;
            }
        }
        __syncthreads();
        if (tid == 0) done_flag(&g_flags[3 + b]);

    } else if (bid < BID_CONS) {
        // ------------- PRODUCER: V proj + softmax + attention ----------
        const int pid = bid - BID_PROD;
        const int h = pid % NH, b = pid / NH;
        const int bm = b * 128, bn = h * 64;

        if (tid == 0) {
            wait_flag(&g_flags[3 + b], 16u);
            wait_flag(&g_flags[1], 32u);
        }
        __syncthreads();

        const float* lg = g_lg + ((size_t)b * NH + h) * NS;
        float l = -1e30f;
        if (tid >= 1 && tid < NS) l = lg[tid];
        float wmx = l;
#pragma unroll
        for (int off = 16; off > 0; off >>= 1)
            wmx = fmaxf(wmx, __shfl_xor_sync(0xFFFFFFFF, wmx, off));
        if (lane == 0 && w < 4) spart[w] = wmx;
        __syncthreads();
        const float m = fmaxf(fmaxf(spart[0], spart[1]), fmaxf(spart[2], spart[3]));
        const float pe = (tid >= 1 && tid < NS) ? expf(l - m) : 0.f;
        if (tid < NS) sp[tid] = pe;
        float ws = pe;
#pragma unroll
        for (int off = 16; off > 0; off >>= 1)
            ws += __shfl_xor_sync(0xFFFFFFFF, ws, off);
        if (lane == 0 && w < 4) spart[4 + w] = ws;
        __syncthreads();

        float acc[2][4][4];
        gemm_main(g_nvf, g_Wvf, sm, bm, bn, acc);

        float* sVt = (float*)sm;
        const int r_base = wm * 32 + (lane >> 2);
        const int c_base = wn * 32 + ((lane & 3) << 1);
#pragma unroll
        for (int mt = 0; mt < 2; mt++)
#pragma unroll
            for (int nt = 0; nt < 4; nt++) {
                const int c = c_base + nt * 8;
                const float b0 = bv[bn + c], b1 = bv[bn + c + 1];
                const int r0 = r_base + mt * 16;
                *(float2*)&sVt[r0 * 64 + c] =
                    make_float2(acc[mt][nt][0] + b0, acc[mt][nt][1] + b1);
                *(float2*)&sVt[(r0 + 8) * 64 + c] =
                    make_float2(acc[mt][nt][2] + b0, acc[mt][nt][3] + b1);
            }
        __syncthreads();

        const float S = spart[4] + spart[5] + spart[6] + spart[7];
        const int d = tid & 63;
        const int q = tid >> 6;
        float av = 0.f;
#pragma unroll 4
        for (int j = q; j < NS; j += 4) av += sp[j] * sVt[j * 64 + d];
        sred[tid] = av;
        __syncthreads();
        if (tid < HD)
            svs[tid] = sred[tid] + sred[tid + 64] + sred[tid + 128] + sred[tid + 192];
        __syncthreads();

        const float vs = svs[d];
        __half* pAf = g_Af + ((size_t)b * NS) * ND + bn + d;
#pragma unroll 4
        for (int i = q; i < NS; i += 4) {
            const float pi = sp[i];
            const float val = __fdividef(vs - pi * sVt[i * 64 + d], S - pi);
            pAf[(size_t)i * ND] = __float2half(val);
        }
        __syncthreads();
        if (tid == 0) done_flag(&g_flags[35 + b]);

    } else {
        // ---------------- CONSUMER: out projection ----------------
        const int cid = bid - BID_CONS;
        const int bn = (cid % 12) * 64;
        const int b  = cid / 12;
        const int bm = b * 128;

        if (tid == 0) {
            wait_flag(&g_flags[35 + b], 12u);
            wait_flag(&g_flags[2], 32u);
        }
        __syncthreads();

        float acc[2][4][4];
        gemm_main(g_Af, g_Wof, sm, bm, bn, acc);

        const int erow = bm + wm * 32 + (lane >> 2);
        const int ecol0 = bn + wn * 32 + ((lane & 3) << 1);
#pragma unroll
        for (int mt = 0; mt < 2; mt++)
#pragma unroll
            for (int nt = 0; nt < 4; nt++) {
                const int col = ecol0 + nt * 8;
                const float b0 = bo[col], b1 = bo[col + 1];
                const int r0 = erow + mt * 16;
                *(float2*)(out + (size_t)r0 * ND + col) =
                    make_float2(acc[mt][nt][0] + b0, acc[mt][nt][1] + b1);
                *(float2*)(out + (size_t)(r0 + 8) * ND + col) =
                    make_float2(acc[mt][nt][2] + b0, acc[mt][nt][3] + b1);
            }
    }
}

// ---------------------------------------------------------------------------
extern "C" void kernel_launch(void* const* d_in, const int* in_sizes, int n_in,
                              void* d_out, int out_size)
{
    const float* desc = (const float*)d_in[0];
    const float* nv   = (const float*)d_in[1];
    // d_in[2]=Wq, d_in[3]=bq dead; d_in[11]=ba dead (cancel in softmax)
    const float* Wk   = (const float*)d_in[4];
    const float* bk   = (const float*)d_in[5];
    const float* Wv   = (const float*)d_in[6];
    const float* bv   = (const float*)d_in[7];
    const float* Wo   = (const float*)d_in[8];
    const float* bo   = (const float*)d_in[9];
    const float* Wa   = (const float*)d_in[10];
    float* out = (float*)d_out;

    // dyn smem: 3 GEMM stages (72KB) > score phase need (48KB)
    cudaFuncSetAttribute(fused_all, cudaFuncAttributeMaxDynamicSharedMemorySize, 3 * STG);

    unsigned* pflag;
    cudaGetSymbolAddress((void**)&pflag, g_flags);
    cudaMemsetAsync(pflag, 0, (3 + NB + NB) * sizeof(unsigned), 0);

    fused_all<<<GRID_TOT, 256, 3 * STG>>>(desc, nv, Wk, bk, Wv, bv, Wo, bo, Wa, out);
}